// round 2
// baseline (speedup 1.0000x reference)
#include <cuda_runtime.h>
#include <math.h>

// Problem constants (fixed by the reference setup_inputs)
#define BB 1
#define VV 3
#define CC 32
#define DD 48
#define HH 128
#define WW 160
#define HW (HH*WW)

// Cost-kernel tiling
#define TW 16
#define TH 4
#define EW (TW+2)
#define EH (TH+2)
#define RPAD 29          // 27 taps padded to 29 (odd -> conflict-free LDS)

// Scratch (static device globals — no runtime allocation)
__device__ float g_featT[VV * HW * CC];          // (v, h, w, c)   7.9 MB
__device__ float g_var[(size_t)DD * HW * CC];    // (d, h, w, c) 125.8 MB
__device__ float g_cost[(size_t)DD * HW];        // (d, h, w)      3.9 MB
__device__ float g_rt[(VV - 1) * 12];            // per src view: rot[9], trans[3]

// ---------------------------------------------------------------------------
// Kernel 0: rot/trans = src_proj @ inv(ref_proj)  (single thread)
// ---------------------------------------------------------------------------
__global__ void k_setup(const float* __restrict__ proj) {
    if (threadIdx.x != 0 || blockIdx.x != 0) return;
    double a[4][8];
    for (int i = 0; i < 4; i++)
        for (int j = 0; j < 4; j++) {
            a[i][j] = (double)proj[i * 4 + j];       // ref_proj = proj[b=0,v=0]
            a[i][4 + j] = (i == j) ? 1.0 : 0.0;
        }
    for (int col = 0; col < 4; col++) {
        int piv = col; double best = fabs(a[col][col]);
        for (int r = col + 1; r < 4; r++) {
            double v = fabs(a[r][col]);
            if (v > best) { best = v; piv = r; }
        }
        if (piv != col)
            for (int j = 0; j < 8; j++) { double t = a[col][j]; a[col][j] = a[piv][j]; a[piv][j] = t; }
        double inv = 1.0 / a[col][col];
        for (int j = 0; j < 8; j++) a[col][j] *= inv;
        for (int r = 0; r < 4; r++) {
            if (r == col) continue;
            double f = a[r][col];
            for (int j = 0; j < 8; j++) a[r][j] -= f * a[col][j];
        }
    }
    for (int v = 1; v < VV; v++) {
        const float* P = proj + v * 16;
        for (int i = 0; i < 3; i++) {
            double m[4];
            for (int j = 0; j < 4; j++) {
                double s = 0.0;
                for (int k = 0; k < 4; k++) s += (double)P[i * 4 + k] * a[k][4 + j];
                m[j] = s;
            }
            g_rt[(v - 1) * 12 + i * 3 + 0] = (float)m[0];
            g_rt[(v - 1) * 12 + i * 3 + 1] = (float)m[1];
            g_rt[(v - 1) * 12 + i * 3 + 2] = (float)m[2];
            g_rt[(v - 1) * 12 + 9 + i]     = (float)m[3];
        }
    }
}

// ---------------------------------------------------------------------------
// Kernel 1: transpose features (v,c,h,w) -> (v,hw,c)
// ---------------------------------------------------------------------------
__global__ void k_transpose(const float* __restrict__ feat) {
    __shared__ float tile[32][33];
    int v   = blockIdx.y;
    int hw0 = blockIdx.x * 32;
    int tx = threadIdx.x, ty = threadIdx.y;
    tile[ty][tx] = feat[((size_t)v * CC + ty) * HW + hw0 + tx];
    __syncthreads();
    g_featT[(size_t)v * HW * CC + (size_t)(hw0 + ty) * CC + tx] = tile[tx][ty];
}

// ---------------------------------------------------------------------------
// Kernel 2: warp + variance, lane layout = (pixel, channel-chunk).
// Block: 160 thr = 20 pixels x 8 chunks.  Warp = 4 pixels x 8 chunks ->
// every corner load is 4 contiguous 128B lines (zero sector waste) and the
// var store is one contiguous 512B warp store.
// ---------------------------------------------------------------------------
__global__ void k_variance(const float* __restrict__ dvals) {
    const int j = threadIdx.x & 7;          // channel chunk (float4)
    const int p = threadIdx.x >> 3;         // pixel in group (0..19)
    const int w = blockIdx.x * 20 + p;
    const int h = blockIdx.y;
    const int d = blockIdx.z;
    const float dv = dvals[d];

    float wgt[2][4];
    int   off[2][4];
#pragma unroll
    for (int v = 0; v < 2; v++) {
        const float* rt = g_rt + v * 12;
        float x = (float)w, y = (float)h;
        float rx = rt[0] * x + rt[1] * y + rt[2];
        float ry = rt[3] * x + rt[4] * y + rt[5];
        float rz = rt[6] * x + rt[7] * y + rt[8];
        float px = rx * dv + rt[9];
        float py = ry * dv + rt[10];
        float pz = rz * dv + rt[11];
        float gx = px / pz, gy = py / pz;
        float x0 = floorf(gx), y0 = floorf(gy);
        float fx = gx - x0, fy = gy - y0;
        float xs[2] = { x0, x0 + 1.f };
        float ys[2] = { y0, y0 + 1.f };
        float wx[2] = { 1.f - fx, fx };
        float wy[2] = { 1.f - fy, fy };
#pragma unroll
        for (int cy = 0; cy < 2; cy++)
#pragma unroll
            for (int cx = 0; cx < 2; cx++) {
                bool valid = (xs[cx] >= 0.f) && (xs[cx] <= (float)(WW - 1)) &&
                             (ys[cy] >= 0.f) && (ys[cy] <= (float)(HH - 1));
                int xi = (int)fminf(fmaxf(xs[cx], 0.f), (float)(WW - 1));
                int yi = (int)fminf(fmaxf(ys[cy], 0.f), (float)(HH - 1));
                wgt[v][cy * 2 + cx] = valid ? wx[cx] * wy[cy] : 0.f;
                off[v][cy * 2 + cx] = (yi * WW + xi) * CC + j * 4;
            }
    }

    float4 r = *(const float4*)(g_featT + (size_t)(h * WW + w) * CC + j * 4);
    const float* f1 = g_featT + (size_t)1 * HW * CC;
    const float* f2 = g_featT + (size_t)2 * HW * CC;

    float4 s = r;
    float4 q = make_float4(r.x * r.x, r.y * r.y, r.z * r.z, r.w * r.w);
    {
        float4 a = *(const float4*)(f1 + off[0][0]);
        float4 b = *(const float4*)(f1 + off[0][1]);
        float4 c = *(const float4*)(f1 + off[0][2]);
        float4 e = *(const float4*)(f1 + off[0][3]);
        float4 val;
        val.x = a.x * wgt[0][0] + b.x * wgt[0][1] + c.x * wgt[0][2] + e.x * wgt[0][3];
        val.y = a.y * wgt[0][0] + b.y * wgt[0][1] + c.y * wgt[0][2] + e.y * wgt[0][3];
        val.z = a.z * wgt[0][0] + b.z * wgt[0][1] + c.z * wgt[0][2] + e.z * wgt[0][3];
        val.w = a.w * wgt[0][0] + b.w * wgt[0][1] + c.w * wgt[0][2] + e.w * wgt[0][3];
        s.x += val.x; s.y += val.y; s.z += val.z; s.w += val.w;
        q.x += val.x * val.x; q.y += val.y * val.y;
        q.z += val.z * val.z; q.w += val.w * val.w;
    }
    {
        float4 a = *(const float4*)(f2 + off[1][0]);
        float4 b = *(const float4*)(f2 + off[1][1]);
        float4 c = *(const float4*)(f2 + off[1][2]);
        float4 e = *(const float4*)(f2 + off[1][3]);
        float4 val;
        val.x = a.x * wgt[1][0] + b.x * wgt[1][1] + c.x * wgt[1][2] + e.x * wgt[1][3];
        val.y = a.y * wgt[1][0] + b.y * wgt[1][1] + c.y * wgt[1][2] + e.y * wgt[1][3];
        val.z = a.z * wgt[1][0] + b.z * wgt[1][1] + c.z * wgt[1][2] + e.z * wgt[1][3];
        val.w = a.w * wgt[1][0] + b.w * wgt[1][1] + c.w * wgt[1][2] + e.w * wgt[1][3];
        s.x += val.x; s.y += val.y; s.z += val.z; s.w += val.w;
        q.x += val.x * val.x; q.y += val.y * val.y;
        q.z += val.z * val.z; q.w += val.w * val.w;
    }
    const float invV = 1.f / (float)VV;
    float4 var;
    float mx = s.x * invV, my = s.y * invV, mz = s.z * invV, mw = s.w * invV;
    var.x = q.x * invV - mx * mx;
    var.y = q.y * invV - my * my;
    var.z = q.z * invV - mz * mz;
    var.w = q.w * invV - mw * mw;
    *(float4*)(g_var + ((size_t)d * HW + h * WW + w) * CC + j * 4) = var;
}

// ---------------------------------------------------------------------------
// Kernel 3: conv via channel-first reduction ("s-fields").
// s[tap](z) = dot(w_tap, var(z)); cost(d,h,w) = sum_taps s[tap](z_tap).
// Each var vector is read from gmem exactly once per block; taps are scalars
// staged in a shared 3-slab ring over the (h,w) tile while sliding along d.
// ---------------------------------------------------------------------------
__device__ __forceinline__ unsigned long long ffma2(unsigned long long a,
                                                    unsigned long long b,
                                                    unsigned long long c) {
    unsigned long long d;
    asm("fma.rn.f32x2 %0, %1, %2, %3;" : "=l"(d) : "l"(a), "l"(b), "l"(c));
    return d;
}

__global__ void k_cost(const float* __restrict__ wgt, const float* __restrict__ bias) {
    __shared__ __align__(16) float sw[27 * 32];        // [tap][c]
    __shared__ float ring[3][EH][EW][RPAD];            // s27 slabs

    const int tid = threadIdx.x;     // 128 threads
    const int w0 = blockIdx.x * TW;
    const int h0 = blockIdx.y * TH;

    // weights: gmem c*27+tap -> sw[tap*32+c]
    for (int i = tid; i < 864; i += 128) {
        int c = i / 27, tap = i % 27;
        sw[tap * 32 + c] = wgt[i];
    }
    // pre-zero slot for virtual slab z=-1  (slot((-1%3)+3)%3 == 2)
    for (int i = tid; i < EH * EW * RPAD; i += 128)
        ((float*)ring[2])[i] = 0.f;
    __syncthreads();

    const float b0 = bias[0];
    const int eh = tid / EW;         // valid for tid < 108
    const int ew = tid - eh * EW;
    const int gh = h0 - 1 + eh;
    const int gw = w0 - 1 + ew;
    const bool pt_ok = (tid < EH * EW) &&
                       (gh >= 0) && (gh < HH) && (gw >= 0) && (gw < WW);

    const int oh = tid / TW;         // valid for tid < 64
    const int ow = tid - oh * TW;

    for (int zd = 0; zd <= DD; zd++) {
        const int slot = zd % 3;
        // ---- compute phase: s27 for slab zd ----
        if (tid < EH * EW) {
            if (zd < DD && pt_ok) {
                const ulonglong2* vp = (const ulonglong2*)
                    (g_var + ((size_t)zd * HW + gh * WW + gw) * CC);
                ulonglong2 v[8];
#pragma unroll
                for (int k = 0; k < 8; k++) v[k] = vp[k];
#pragma unroll
                for (int tap = 0; tap < 27; tap++) {
                    const ulonglong2* wp = (const ulonglong2*)(sw + tap * 32);
                    unsigned long long acc = 0ull;
#pragma unroll
                    for (int k = 0; k < 8; k++) {
                        ulonglong2 ww = wp[k];
                        acc = ffma2(v[k].x, ww.x, acc);
                        acc = ffma2(v[k].y, ww.y, acc);
                    }
                    float lo, hi;
                    asm("mov.b64 {%0,%1}, %2;" : "=f"(lo), "=f"(hi) : "l"(acc));
                    ring[slot][eh][ew][tap] = lo + hi;
                }
            } else {
#pragma unroll
                for (int tap = 0; tap < 27; tap++)
                    ring[slot][eh][ew][tap] = 0.f;
            }
        }
        __syncthreads();
        // ---- emit phase: cost for d = zd-1 ----
        if (zd >= 1 && tid < TH * TW) {
            const int d = zd - 1;
            float sum = b0;
#pragma unroll
            for (int kd = 0; kd < 3; kd++) {
                const int sl = (d - 1 + kd + 3) % 3;
#pragma unroll
                for (int kh = 0; kh < 3; kh++)
#pragma unroll
                    for (int kw = 0; kw < 3; kw++)
                        sum += ring[sl][oh + kh][ow + kw][kd * 9 + kh * 3 + kw];
            }
            g_cost[(size_t)d * HW + (h0 + oh) * WW + (w0 + ow)] = sum;
        }
        __syncthreads();
    }
}

// ---------------------------------------------------------------------------
// Kernel 4: softmax over D + depth regression + window-4 confidence
// ---------------------------------------------------------------------------
__global__ void k_post(const float* __restrict__ dvals, float* __restrict__ out) {
    int hw = blockIdx.x * blockDim.x + threadIdx.x;
    if (hw >= HW) return;
    float c[DD];
    float m = -1e30f;
#pragma unroll
    for (int d = 0; d < DD; d++) {
        c[d] = g_cost[(size_t)d * HW + hw];
        m = fmaxf(m, c[d]);
    }
    float se = 0.f;
#pragma unroll
    for (int d = 0; d < DD; d++) { c[d] = expf(c[d] - m); se += c[d]; }
    float inv = 1.f / se;
    float depth = 0.f, fi = 0.f;
#pragma unroll
    for (int d = 0; d < DD; d++) {
        c[d] *= inv;
        depth += c[d] * dvals[d];
        fi += c[d] * (float)d;
    }
    int di = (int)fi;
    di = min(max(di, 0), DD - 1);
    float conf = 0.f;
#pragma unroll
    for (int d = 0; d < DD; d++) {
        bool in = (d >= di - 1) && (d <= di + 2);
        conf += in ? c[d] : 0.f;
    }
    out[hw]      = depth;
    out[HW + hw] = conf;
}

// ---------------------------------------------------------------------------
extern "C" void kernel_launch(void* const* d_in, const int* in_sizes, int n_in,
                              void* d_out, int out_size) {
    const float* features = (const float*)d_in[0];   // (1,3,32,128,160)
    const float* proj     = (const float*)d_in[1];   // (1,3,4,4)
    const float* dvals    = (const float*)d_in[2];   // (1,48)
    const float* rweight  = (const float*)d_in[3];   // (1,32,3,3,3)
    const float* rbias    = (const float*)d_in[4];   // (1,)
    float* out = (float*)d_out;                      // depth(20480) ++ conf(20480)

    k_setup<<<1, 32>>>(proj);
    k_transpose<<<dim3(HW / 32, VV), dim3(32, 32)>>>(features);
    k_variance<<<dim3(WW / 20, HH, DD), 160>>>(dvals);
    k_cost<<<dim3(WW / TW, HH / TH), 128>>>(rweight, rbias);
    k_post<<<(HW + 255) / 256, 256>>>(dvals, out);
}

// round 14
// speedup vs baseline: 1.9351x; 1.9351x over previous
#include <cuda_runtime.h>
#include <math.h>

// Problem constants (fixed by the reference setup_inputs)
#define BB 1
#define VV 3
#define CC 32
#define DD 48
#define HH 128
#define WW 160
#define HW (HH*WW)
#define DHW ((size_t)DD*HW)

#define RS 29              // s27 row stride (29 odd -> conflict-free)

// Scratch (static device globals — no runtime allocation)
__device__ float g_featT[VV * HW * CC];            // (v, h, w, c)    7.9 MB
__device__ float g_t[9 * DHW];                     // (tap9, z, y, x) 35.4 MB
__device__ float g_rt[(VV - 1) * 12];              // per src view: rot[9], trans[3]

// ---------------------------------------------------------------------------
// packed f32x2 helpers
// ---------------------------------------------------------------------------
__device__ __forceinline__ unsigned long long pk(float lo, float hi) {
    unsigned long long r;
    asm("mov.b64 %0,{%1,%2};" : "=l"(r) : "f"(lo), "f"(hi));
    return r;
}
__device__ __forceinline__ void upk(unsigned long long v, float& lo, float& hi) {
    asm("mov.b64 {%0,%1},%2;" : "=f"(lo), "=f"(hi) : "l"(v));
}
__device__ __forceinline__ unsigned long long mul2(unsigned long long a, unsigned long long b) {
    unsigned long long d;
    asm("mul.rn.f32x2 %0,%1,%2;" : "=l"(d) : "l"(a), "l"(b));
    return d;
}
__device__ __forceinline__ unsigned long long add2(unsigned long long a, unsigned long long b) {
    unsigned long long d;
    asm("add.rn.f32x2 %0,%1,%2;" : "=l"(d) : "l"(a), "l"(b));
    return d;
}
__device__ __forceinline__ unsigned long long fma2(unsigned long long a, unsigned long long b,
                                                   unsigned long long c) {
    unsigned long long d;
    asm("fma.rn.f32x2 %0,%1,%2,%3;" : "=l"(d) : "l"(a), "l"(b), "l"(c));
    return d;
}

// ---------------------------------------------------------------------------
// Kernel 0: rot/trans = src_proj @ inv(ref_proj)  (cofactor inverse, 1 thread)
// ---------------------------------------------------------------------------
__global__ void k_setup(const float* __restrict__ proj) {
    if (threadIdx.x != 0 || blockIdx.x != 0) return;
    double m[16], inv[16];
    for (int i = 0; i < 16; i++) m[i] = (double)proj[i];   // ref_proj (b=0,v=0)

    inv[0]  =  m[5]*m[10]*m[15] - m[5]*m[11]*m[14] - m[9]*m[6]*m[15] + m[9]*m[7]*m[14] + m[13]*m[6]*m[11] - m[13]*m[7]*m[10];
    inv[4]  = -m[4]*m[10]*m[15] + m[4]*m[11]*m[14] + m[8]*m[6]*m[15] - m[8]*m[7]*m[14] - m[12]*m[6]*m[11] + m[12]*m[7]*m[10];
    inv[8]  =  m[4]*m[9]*m[15]  - m[4]*m[11]*m[13] - m[8]*m[5]*m[15] + m[8]*m[7]*m[13] + m[12]*m[5]*m[11] - m[12]*m[7]*m[9];
    inv[12] = -m[4]*m[9]*m[14]  + m[4]*m[10]*m[13] + m[8]*m[5]*m[14] - m[8]*m[6]*m[13] - m[12]*m[5]*m[10] + m[12]*m[6]*m[9];
    inv[1]  = -m[1]*m[10]*m[15] + m[1]*m[11]*m[14] + m[9]*m[2]*m[15] - m[9]*m[3]*m[14] - m[13]*m[2]*m[11] + m[13]*m[3]*m[10];
    inv[5]  =  m[0]*m[10]*m[15] - m[0]*m[11]*m[14] - m[8]*m[2]*m[15] + m[8]*m[3]*m[14] + m[12]*m[2]*m[11] - m[12]*m[3]*m[10];
    inv[9]  = -m[0]*m[9]*m[15]  + m[0]*m[11]*m[13] + m[8]*m[1]*m[15] - m[8]*m[3]*m[13] - m[12]*m[1]*m[11] + m[12]*m[3]*m[9];
    inv[13] =  m[0]*m[9]*m[14]  - m[0]*m[10]*m[13] - m[8]*m[1]*m[14] + m[8]*m[2]*m[13] + m[12]*m[1]*m[10] - m[12]*m[2]*m[9];
    inv[2]  =  m[1]*m[6]*m[15]  - m[1]*m[7]*m[14]  - m[5]*m[2]*m[15] + m[5]*m[3]*m[14] + m[13]*m[2]*m[7]  - m[13]*m[3]*m[6];
    inv[6]  = -m[0]*m[6]*m[15]  + m[0]*m[7]*m[14]  + m[4]*m[2]*m[15] - m[4]*m[3]*m[14] - m[12]*m[2]*m[7]  + m[12]*m[3]*m[6];
    inv[10] =  m[0]*m[5]*m[15]  - m[0]*m[7]*m[13]  - m[4]*m[1]*m[15] + m[4]*m[3]*m[13] + m[12]*m[1]*m[7]  - m[12]*m[3]*m[5];
    inv[14] = -m[0]*m[5]*m[14]  + m[0]*m[6]*m[13]  + m[4]*m[1]*m[14] - m[4]*m[2]*m[13] - m[12]*m[1]*m[6]  + m[12]*m[2]*m[5];
    inv[3]  = -m[1]*m[6]*m[11]  + m[1]*m[7]*m[10]  + m[5]*m[2]*m[11] - m[5]*m[3]*m[10] - m[9]*m[2]*m[7]   + m[9]*m[3]*m[6];
    inv[7]  =  m[0]*m[6]*m[11]  - m[0]*m[7]*m[10]  - m[4]*m[2]*m[11] + m[4]*m[3]*m[10] + m[8]*m[2]*m[7]   - m[8]*m[3]*m[6];
    inv[11] = -m[0]*m[5]*m[11]  + m[0]*m[7]*m[9]   + m[4]*m[1]*m[11] - m[4]*m[3]*m[9]  - m[8]*m[1]*m[7]   + m[8]*m[3]*m[5];
    inv[15] =  m[0]*m[5]*m[10]  - m[0]*m[6]*m[9]   - m[4]*m[1]*m[10] + m[4]*m[2]*m[9]  + m[8]*m[1]*m[6]   - m[8]*m[2]*m[5];

    double det = m[0]*inv[0] + m[1]*inv[4] + m[2]*inv[8] + m[3]*inv[12];
    double id = 1.0 / det;
    for (int i = 0; i < 16; i++) inv[i] *= id;

    for (int v = 1; v < VV; v++) {
        const float* P = proj + v * 16;
        for (int i = 0; i < 3; i++) {
            double r[4];
            for (int j = 0; j < 4; j++) {
                double s = 0.0;
                for (int k = 0; k < 4; k++) s += (double)P[i * 4 + k] * inv[k * 4 + j];
                r[j] = s;
            }
            g_rt[(v - 1) * 12 + i * 3 + 0] = (float)r[0];
            g_rt[(v - 1) * 12 + i * 3 + 1] = (float)r[1];
            g_rt[(v - 1) * 12 + i * 3 + 2] = (float)r[2];
            g_rt[(v - 1) * 12 + 9 + i]     = (float)r[3];
        }
    }
}

// ---------------------------------------------------------------------------
// Kernel 1: transpose features (v,c,h,w) -> (v,hw,c)
// ---------------------------------------------------------------------------
__global__ void k_transpose(const float* __restrict__ feat) {
    __shared__ float tile[32][33];
    int v   = blockIdx.y;
    int hw0 = blockIdx.x * 32;
    int tx = threadIdx.x, ty = threadIdx.y;
    tile[ty][tx] = feat[((size_t)v * CC + ty) * HW + hw0 + tx];
    __syncthreads();
    g_featT[(size_t)v * HW * CC + (size_t)(hw0 + ty) * CC + tx] = tile[tx][ty];
}

// ---------------------------------------------------------------------------
// Kernel 2 (fused): warp + variance + 27 channel-dots + kw-combine -> t9.
// One block per (z,y) row. Phase1: chunk-lane gathers into smem row buffer.
// Phase2: per-pixel 27 tap dots from registers (packed f32x2), s27 -> smem.
// Phase3: kw-combine -> 9 coalesced stores.
// ---------------------------------------------------------------------------
__global__ __launch_bounds__(160, 5) void k_vt9(const float* __restrict__ dvals,
                                                const float* __restrict__ wgt) {
    __shared__ __align__(16) float sw[27 * 32];    // [tap][c]
    __shared__ __align__(16) float buf[160 * 33];  // phase1: var[x][33]; phase3 alias: s[162][RS]

    const int tid = threadIdx.x;
    const int z = blockIdx.x;     // depth slab
    const int y = blockIdx.y;     // row
    const float dv = dvals[z];

    // weights: gmem c*27+tap -> sw[tap*32+c]
    for (int i = tid; i < 864; i += 160) {
        int c = i / 27, tap = i % 27;
        sw[tap * 32 + c] = wgt[i];
    }

    // per-view linear projection coefficients:  p(x) = A*x + B
    float Ax[2], Bx[2], Ay[2], By[2], Az[2], Bz[2];
#pragma unroll
    for (int v = 0; v < 2; v++) {
        const float* rt = g_rt + v * 12;
        float yf = (float)y;
        Ax[v] = rt[0] * dv;  Bx[v] = (rt[1] * yf + rt[2]) * dv + rt[9];
        Ay[v] = rt[3] * dv;  By[v] = (rt[4] * yf + rt[5]) * dv + rt[10];
        Az[v] = rt[6] * dv;  Bz[v] = (rt[7] * yf + rt[8]) * dv + rt[11];
    }

    const int j   = tid & 7;      // channel chunk (float4)
    const int p20 = tid >> 3;     // pixel within 20-group
    const float* f1 = g_featT + (size_t)1 * HW * CC;
    const float* f2 = g_featT + (size_t)2 * HW * CC;
    const unsigned long long IV  = pk(1.f / 3.f, 1.f / 3.f);
    const unsigned long long NIV = pk(-1.f / 3.f, -1.f / 3.f);

    // ---- phase 1: variance per (pixel, chunk) into buf ----
#pragma unroll 1
    for (int it = 0; it < 8; it++) {
        const int x = it * 20 + p20;
        const float xf = (float)x;

        float cw[2][4];
        int   co[2][4];
#pragma unroll
        for (int v = 0; v < 2; v++) {
            float pz = Az[v] * xf + Bz[v];
            float gx = (Ax[v] * xf + Bx[v]) / pz;
            float gy = (Ay[v] * xf + By[v]) / pz;
            float x0 = floorf(gx), y0 = floorf(gy);
            float fx = gx - x0, fy = gy - y0;
            float xs[2] = { x0, x0 + 1.f };
            float ys[2] = { y0, y0 + 1.f };
            float wx[2] = { 1.f - fx, fx };
            float wy[2] = { 1.f - fy, fy };
#pragma unroll
            for (int cy = 0; cy < 2; cy++)
#pragma unroll
                for (int cx = 0; cx < 2; cx++) {
                    bool valid = (xs[cx] >= 0.f) && (xs[cx] <= (float)(WW - 1)) &&
                                 (ys[cy] >= 0.f) && (ys[cy] <= (float)(HH - 1));
                    int xi = (int)fminf(fmaxf(xs[cx], 0.f), (float)(WW - 1));
                    int yi = (int)fminf(fmaxf(ys[cy], 0.f), (float)(HH - 1));
                    cw[v][cy * 2 + cx] = valid ? wx[cx] * wy[cy] : 0.f;
                    co[v][cy * 2 + cx] = (yi * WW + xi) * CC + j * 4;
                }
        }

        ulonglong2 r = *(const ulonglong2*)(g_featT + (size_t)(y * WW + x) * CC + j * 4);
        unsigned long long slo = r.x, shi = r.y;
        unsigned long long qlo = mul2(r.x, r.x), qhi = mul2(r.y, r.y);
#pragma unroll
        for (int v = 0; v < 2; v++) {
            const float* fp = (v == 0) ? f1 : f2;
            ulonglong2 a = *(const ulonglong2*)(fp + co[v][0]);
            ulonglong2 b = *(const ulonglong2*)(fp + co[v][1]);
            ulonglong2 c = *(const ulonglong2*)(fp + co[v][2]);
            ulonglong2 e = *(const ulonglong2*)(fp + co[v][3]);
            unsigned long long w0 = pk(cw[v][0], cw[v][0]);
            unsigned long long w1 = pk(cw[v][1], cw[v][1]);
            unsigned long long w2 = pk(cw[v][2], cw[v][2]);
            unsigned long long w3 = pk(cw[v][3], cw[v][3]);
            unsigned long long vlo = mul2(a.x, w0);
            vlo = fma2(b.x, w1, vlo); vlo = fma2(c.x, w2, vlo); vlo = fma2(e.x, w3, vlo);
            unsigned long long vhi = mul2(a.y, w0);
            vhi = fma2(b.y, w1, vhi); vhi = fma2(c.y, w2, vhi); vhi = fma2(e.y, w3, vhi);
            slo = add2(slo, vlo); shi = add2(shi, vhi);
            qlo = fma2(vlo, vlo, qlo); qhi = fma2(vhi, vhi, qhi);
        }
        // var = q/3 - (s/3)^2  = (-s/3)*(s/3) + q/3
        unsigned long long mlo = mul2(slo, IV),  mhi = mul2(shi, IV);
        unsigned long long nlo = mul2(slo, NIV), nhi = mul2(shi, NIV);
        unsigned long long vrl = fma2(nlo, mlo, mul2(qlo, IV));
        unsigned long long vrh = fma2(nhi, mhi, mul2(qhi, IV));
        float v0, v1, v2, v3;
        upk(vrl, v0, v1); upk(vrh, v2, v3);
        float* dst = buf + x * 33 + j * 4;
        dst[0] = v0; dst[1] = v1; dst[2] = v2; dst[3] = v3;
    }
    __syncthreads();

    // ---- phase 2: read own pixel's 32 channels, then alias buf as s27 ----
    const int w = tid;
    unsigned long long v[16];
#pragma unroll
    for (int k = 0; k < 16; k++)
        v[k] = pk(buf[w * 33 + 2 * k], buf[w * 33 + 2 * k + 1]);
    __syncthreads();            // everyone done reading var; buf becomes s

    float* s = buf;             // s[(x+1)*RS + tap], x in [-1, 160]
    if (tid < 2) {
        int row = (tid == 0) ? 0 : 161;
#pragma unroll
        for (int tap = 0; tap < 27; tap++) s[row * RS + tap] = 0.f;
    }
#pragma unroll 9
    for (int tap = 0; tap < 27; tap++) {
        const unsigned long long* wp = (const unsigned long long*)(sw + tap * 32);
        unsigned long long acc = 0ull;
#pragma unroll
        for (int k = 0; k < 16; k++) acc = fma2(v[k], wp[k], acc);
        float lo, hi; upk(acc, lo, hi);
        s[(w + 1) * RS + tap] = lo + hi;
    }
    __syncthreads();

    // ---- phase 3: kw-combine -> t9, coalesced stores ----
    const size_t base = (size_t)z * HW + y * WW + w;
#pragma unroll
    for (int kd = 0; kd < 3; kd++)
#pragma unroll
        for (int kh = 0; kh < 3; kh++) {
            int tb = kd * 9 + kh * 3;
            float t = s[w * RS + tb] + s[(w + 1) * RS + tb + 1] + s[(w + 2) * RS + tb + 2];
            g_t[(size_t)(kd * 3 + kh) * DHW + base] = t;
        }
}

// ---------------------------------------------------------------------------
// Kernel 3: gather t9 -> cost, softmax over D, depth regression, confidence
// ---------------------------------------------------------------------------
__global__ void k_post(const float* __restrict__ dvals, const float* __restrict__ bias,
                       float* __restrict__ out) {
    int hw = blockIdx.x * blockDim.x + threadIdx.x;
    if (hw >= HW) return;
    const int h = hw / WW;
    const int w = hw - h * WW;
    const float b0 = bias[0];

    float c[DD];
#pragma unroll
    for (int d = 0; d < DD; d++) c[d] = b0;

#pragma unroll
    for (int kd = 0; kd < 3; kd++)
#pragma unroll
        for (int kh = 0; kh < 3; kh++) {
            int yy = h + kh - 1;
            if (yy < 0 || yy >= HH) continue;
            const float* tp = g_t + (size_t)(kd * 3 + kh) * DHW + yy * WW + w;
#pragma unroll
            for (int d = 0; d < DD; d++) {
                int zz = d + kd - 1;
                if (zz >= 0 && zz < DD) c[d] += tp[(size_t)zz * HW];
            }
        }

    float m = -1e30f;
#pragma unroll
    for (int d = 0; d < DD; d++) m = fmaxf(m, c[d]);
    float se = 0.f;
#pragma unroll
    for (int d = 0; d < DD; d++) { c[d] = expf(c[d] - m); se += c[d]; }
    float inv = 1.f / se;
    float depth = 0.f, fi = 0.f;
#pragma unroll
    for (int d = 0; d < DD; d++) {
        c[d] *= inv;
        depth += c[d] * dvals[d];
        fi += c[d] * (float)d;
    }
    int di = (int)fi;
    di = min(max(di, 0), DD - 1);
    float conf = 0.f;
#pragma unroll
    for (int d = 0; d < DD; d++) {
        bool in = (d >= di - 1) && (d <= di + 2);
        conf += in ? c[d] : 0.f;
    }
    out[hw]      = depth;
    out[HW + hw] = conf;
}

// ---------------------------------------------------------------------------
extern "C" void kernel_launch(void* const* d_in, const int* in_sizes, int n_in,
                              void* d_out, int out_size) {
    const float* features = (const float*)d_in[0];   // (1,3,32,128,160)
    const float* proj     = (const float*)d_in[1];   // (1,3,4,4)
    const float* dvals    = (const float*)d_in[2];   // (1,48)
    const float* rweight  = (const float*)d_in[3];   // (1,32,3,3,3)
    const float* rbias    = (const float*)d_in[4];   // (1,)
    float* out = (float*)d_out;                      // depth(20480) ++ conf(20480)

    k_setup<<<1, 32>>>(proj);
    k_transpose<<<dim3(HW / 32, VV), dim3(32, 32)>>>(features);
    k_vt9<<<dim3(DD, HH), 160>>>(dvals, rweight);
    k_post<<<(HW + 255) / 256, 256>>>(dvals, rbias, out);
}